// round 4
// baseline (speedup 1.0000x reference)
#include <cuda_runtime.h>
#include <cstdint>

#define N_NODES_MAX 100000
#define D_FEAT 128

// Scratch (static __device__ arrays — no allocation per harness rules)
__device__ float  g_pos[N_NODES_MAX];
__device__ float2 g_acc[N_NODES_MAX];   // {sum_dist, count}

// Kernel 1: compact pos column + zero accumulators (runs every launch so
// graph replays are deterministic).
__global__ void k_init(const float* __restrict__ h, int n_nodes) {
    int i = blockIdx.x * blockDim.x + threadIdx.x;
    if (i < n_nodes) {
        g_pos[i] = h[(size_t)i * D_FEAT];
        g_acc[i] = make_float2(0.0f, 0.0f);
    }
}

__device__ __forceinline__ void edge_accum(int s, int d, int n_nodes) {
    // Predicated bounds guard: free in the common case, turns a bad-dtype
    // assumption into a wrong-answer (diagnosable) instead of a crash.
    if ((unsigned)s < (unsigned)n_nodes && (unsigned)d < (unsigned)n_nodes) {
        float dist = fabsf(__ldg(&g_pos[s]) - __ldg(&g_pos[d]));
        float2* p = &g_acc[d];
        asm volatile("red.global.add.v2.f32 [%0], {%1, %2};"
                     :: "l"(p), "f"(dist), "f"(1.0f) : "memory");
    }
}

// Kernel 2: edge scatter. 4 edges per thread via one int4 (16B) load from
// each of src/dst; one vectorized red.global.add.v2.f32 per edge.
__global__ void k_edges(const int* __restrict__ src,
                        const int* __restrict__ dst,
                        int n_edges, int n_nodes) {
    int t = blockIdx.x * blockDim.x + threadIdx.x;
    int e0 = t * 4;
    if (e0 + 3 < n_edges) {
        int4 s4 = *reinterpret_cast<const int4*>(src + e0);
        int4 d4 = *reinterpret_cast<const int4*>(dst + e0);
        edge_accum(s4.x, d4.x, n_nodes);
        edge_accum(s4.y, d4.y, n_nodes);
        edge_accum(s4.z, d4.z, n_nodes);
        edge_accum(s4.w, d4.w, n_nodes);
    } else {
        for (int e = e0; e < n_edges; e++)
            edge_accum(src[e], dst[e], n_nodes);
    }
}

// Kernel 3: finalize output (N, 2): col0 = pos, col1 = sum / max(cnt, 1)
__global__ void k_final(float* __restrict__ out, int n_nodes) {
    int i = blockIdx.x * blockDim.x + threadIdx.x;
    if (i < n_nodes) {
        float2 a = g_acc[i];
        float2 r = make_float2(g_pos[i], a.x / fmaxf(a.y, 1.0f));
        *reinterpret_cast<float2*>(out + 2 * (size_t)i) = r;
    }
}

extern "C" void kernel_launch(void* const* d_in, const int* in_sizes, int n_in,
                              void* d_out, int out_size) {
    const float* h   = (const float*)d_in[0];
    const int*   src = (const int*)d_in[1];
    const int*   dst = (const int*)d_in[2];
    float* out = (float*)d_out;

    int n_nodes = in_sizes[0] / D_FEAT;
    int n_edges = in_sizes[1];

    const int TPB = 256;
    int init_blocks = (n_nodes + TPB - 1) / TPB;
    k_init<<<init_blocks, TPB>>>(h, n_nodes);

    int n_quads = (n_edges + 3) / 4;
    int edge_blocks = (n_quads + TPB - 1) / TPB;
    k_edges<<<edge_blocks, TPB>>>(src, dst, n_edges, n_nodes);

    k_final<<<init_blocks, TPB>>>(out, n_nodes);
}

// round 6
// speedup vs baseline: 1.3810x; 1.3810x over previous
#include <cuda_runtime.h>
#include <cuda_fp16.h>
#include <cstdint>

#define N_NODES_MAX 100000
#define D_FEAT 128

// Scratch (static __device__ arrays — no allocation per harness rules)
__device__ float  g_pos[N_NODES_MAX];    // exact fp32 pos (for output col 0)
__device__ __half g_posh[N_NODES_MAX];   // fp16 pos copy: 200KB, L1-resident for gathers
__device__ float2 g_acc[N_NODES_MAX];    // {sum_dist, count}

// Kernel 1: compact pos column (fp32 + fp16 copies) + zero accumulators.
__global__ void k_init(const float* __restrict__ h, int n_nodes) {
    int i = blockIdx.x * blockDim.x + threadIdx.x;
    if (i < n_nodes) {
        float v = h[(size_t)i * D_FEAT];
        g_pos[i]  = v;
        g_posh[i] = __float2half(v);
        g_acc[i]  = make_float2(0.0f, 0.0f);
    }
}

__device__ __forceinline__ void edge_accum(int s, int d, int n_nodes) {
    if ((unsigned)s < (unsigned)n_nodes && (unsigned)d < (unsigned)n_nodes) {
        float ps = __half2float(__ldg(&g_posh[s]));
        float pd = __half2float(__ldg(&g_posh[d]));
        float dist = fabsf(ps - pd);
        float2* p = &g_acc[d];
        asm volatile("red.global.add.v2.f32 [%0], {%1, %2};"
                     :: "l"(p), "f"(dist), "f"(1.0f) : "memory");
    }
}

// Kernel 2: edge scatter. 8 edges per thread via two int4 (16B) loads from
// each of src/dst; one vectorized red.global.add.v2.f32 per edge.
__global__ void k_edges(const int* __restrict__ src,
                        const int* __restrict__ dst,
                        int n_edges, int n_nodes) {
    int t = blockIdx.x * blockDim.x + threadIdx.x;
    int e0 = t * 8;
    if (e0 + 7 < n_edges) {
        int4 s0 = *reinterpret_cast<const int4*>(src + e0);
        int4 s1 = *reinterpret_cast<const int4*>(src + e0 + 4);
        int4 d0 = *reinterpret_cast<const int4*>(dst + e0);
        int4 d1 = *reinterpret_cast<const int4*>(dst + e0 + 4);
        edge_accum(s0.x, d0.x, n_nodes);
        edge_accum(s0.y, d0.y, n_nodes);
        edge_accum(s0.z, d0.z, n_nodes);
        edge_accum(s0.w, d0.w, n_nodes);
        edge_accum(s1.x, d1.x, n_nodes);
        edge_accum(s1.y, d1.y, n_nodes);
        edge_accum(s1.z, d1.z, n_nodes);
        edge_accum(s1.w, d1.w, n_nodes);
    } else {
        for (int e = e0; e < n_edges; e++)
            edge_accum(src[e], dst[e], n_nodes);
    }
}

// Kernel 3: finalize output (N, 2): col0 = exact fp32 pos, col1 = sum/max(cnt,1)
__global__ void k_final(float* __restrict__ out, int n_nodes) {
    int i = blockIdx.x * blockDim.x + threadIdx.x;
    if (i < n_nodes) {
        float2 a = g_acc[i];
        float2 r = make_float2(g_pos[i], a.x / fmaxf(a.y, 1.0f));
        *reinterpret_cast<float2*>(out + 2 * (size_t)i) = r;
    }
}

extern "C" void kernel_launch(void* const* d_in, const int* in_sizes, int n_in,
                              void* d_out, int out_size) {
    const float* h   = (const float*)d_in[0];
    const int*   src = (const int*)d_in[1];
    const int*   dst = (const int*)d_in[2];
    float* out = (float*)d_out;

    int n_nodes = in_sizes[0] / D_FEAT;
    int n_edges = in_sizes[1];

    const int TPB = 256;
    int init_blocks = (n_nodes + TPB - 1) / TPB;
    k_init<<<init_blocks, TPB>>>(h, n_nodes);

    int n_oct = (n_edges + 7) / 8;
    int edge_blocks = (n_oct + TPB - 1) / TPB;
    k_edges<<<edge_blocks, TPB>>>(src, dst, n_edges, n_nodes);

    k_final<<<init_blocks, TPB>>>(out, n_nodes);
}